// round 6
// baseline (speedup 1.0000x reference)
#include <cuda_runtime.h>
#include <cuda_bf16.h>

#define TPB 256
#define N_MAX 100000

// Packed per-node data: pos.xyz + atom_type (bitcast int in .w).
// 16B aligned -> each random gather is exactly one LDG.128 / one 32B sector.
__device__ float4 g_node[N_MAX];

__global__ void prep_kernel(const float* __restrict__ pos,
                            const int* __restrict__ types,
                            int N, float* __restrict__ out, int G) {
    int i = blockIdx.x * blockDim.x + threadIdx.x;
    if (i < G) out[i] = 0.0f;           // d_out is poisoned -> zero it
    if (i < N) {
        float4 v;
        v.x = pos[3 * i + 0];
        v.y = pos[3 * i + 1];
        v.z = pos[3 * i + 2];
        v.w = __int_as_float(types[i]);
        g_node[i] = v;
    }
}

struct SegAcc {
    float acc;
    int   cur;
};

__device__ __forceinline__ void do_edge(int i0, int i1, int seg,
                                        const float4* __restrict__ s_k,
                                        const float* __restrict__ s_v,
                                        float* __restrict__ out,
                                        SegAcc& st) {
    float4 n0 = g_node[i0];
    float4 n1 = g_node[i1];
    float dx = n0.x - n1.x, dy = n0.y - n1.y, dz = n0.z - n1.z;
    float x  = sqrtf(dx * dx + dy * dy + dz * dz);
    int idx  = __float_as_int(n0.w) * 25 + __float_as_int(n1.w);
    float4 k = s_k[idx];
    float V  = s_v[idx] + x * (k.x + x * (k.y + x * (k.z + x * k.w)));
    if (seg != st.cur) {
        if (st.cur >= 0) atomicAdd(&out[st.cur], st.acc);
        st.acc = 0.0f;
        st.cur = seg;
    }
    st.acc += V;
}

__global__ void __launch_bounds__(TPB)
edge_kernel(const int4* __restrict__ map0,   // mapping row 0, 4 edges per int4
            const int4* __restrict__ map1,   // mapping row 1
            const int4* __restrict__ batch,  // mapping_batch
            const float* __restrict__ ks,    // (4,25,25)
            const float* __restrict__ v0,    // (25,25)
            float* __restrict__ out,
            int nQuads, int quadsPerBlock) {
    __shared__ float4 s_k[625];  // k0..k3 per (t0,t1)
    __shared__ float  s_v[625];  // v0 per (t0,t1)
    for (int i = threadIdx.x; i < 625; i += TPB) {
        s_k[i] = make_float4(ks[i], ks[625 + i], ks[1250 + i], ks[1875 + i]);
        s_v[i] = v0[i];
    }
    __syncthreads();

    int pStart = blockIdx.x * quadsPerBlock + threadIdx.x;
    int pEnd   = min((blockIdx.x + 1) * quadsPerBlock, nQuads);

    // Register accumulator per thread; mapping_batch is sorted so the segment
    // id changes rarely along a thread's walk -> few atomics.
    SegAcc st;
    st.acc = 0.0f;
    st.cur = -1;

    for (int p = pStart; p < pEnd; p += TPB) {
        int4 a = map0[p];
        int4 b = map1[p];
        int4 s = batch[p];
        do_edge(a.x, b.x, s.x, s_k, s_v, out, st);
        do_edge(a.y, b.y, s.y, s_k, s_v, out, st);
        do_edge(a.z, b.z, s.z, s_k, s_v, out, st);
        do_edge(a.w, b.w, s.w, s_k, s_v, out, st);
    }
    if (st.cur >= 0) atomicAdd(&out[st.cur], st.acc);
}

extern "C" void kernel_launch(void* const* d_in, const int* in_sizes, int n_in,
                              void* d_out, int out_size) {
    const float* pos     = (const float*)d_in[0];
    const float* ks      = (const float*)d_in[1];
    const float* v0      = (const float*)d_in[2];
    const int*   mapping = (const int*)d_in[3];   // JAX silently downcasts int64 -> int32
    const int*   types   = (const int*)d_in[4];
    const int*   batch   = (const int*)d_in[5];

    int N = in_sizes[0] / 3;          // 100000
    int E = in_sizes[3] / 2;          // 8,000,000
    int G = out_size;                 // 512
    float* out = (float*)d_out;

    if (N > N_MAX) N = N_MAX;  // defensive; problem shape is fixed

    int nQuads = E / 4;        // E = 8M, divisible by 4

    int prepThreads = (N > G) ? N : G;
    prep_kernel<<<(prepThreads + TPB - 1) / TPB, TPB>>>(pos, types, N, out, G);

    // ~8 blocks per SM on 148 SMs
    int grid = 1184;
    int qpb  = (nQuads + grid - 1) / grid;
    qpb      = ((qpb + TPB - 1) / TPB) * TPB;  // multiple of block width
    grid     = (nQuads + qpb - 1) / qpb;

    edge_kernel<<<grid, TPB>>>((const int4*)mapping,
                               (const int4*)(mapping + E),
                               (const int4*)batch,
                               ks, v0, out, nQuads, qpb);
}

// round 8
// speedup vs baseline: 1.4985x; 1.4985x over previous
#include <cuda_runtime.h>
#include <cuda_bf16.h>

#define TPB 256
#define N_MAX 100000

// Packed per-node data: pos.xyz + atom_type (bitcast int in .w).
// 16B aligned -> each random gather is exactly one LDG.128 / one 32B sector.
__device__ float4 g_node[N_MAX];

__global__ void prep_kernel(const float* __restrict__ pos,
                            const int* __restrict__ types,
                            int N, float* __restrict__ out, int G) {
    int i = blockIdx.x * blockDim.x + threadIdx.x;
    if (i < G) out[i] = 0.0f;           // d_out is poisoned -> zero it
    if (i < N) {
        float4 v;
        v.x = pos[3 * i + 0];
        v.y = pos[3 * i + 1];
        v.z = pos[3 * i + 2];
        v.w = __int_as_float(types[i]);
        g_node[i] = v;
    }
}

__device__ __forceinline__ float poly(const float4& n0, const float4& n1,
                                      const float4* __restrict__ s_k,
                                      const float* __restrict__ s_v) {
    float dx = n0.x - n1.x, dy = n0.y - n1.y, dz = n0.z - n1.z;
    float x  = sqrtf(dx * dx + dy * dy + dz * dz);
    int idx  = __float_as_int(n0.w) * 25 + __float_as_int(n1.w);
    float4 k = s_k[idx];
    return s_v[idx] + x * (k.x + x * (k.y + x * (k.z + x * k.w)));
}

__global__ void __launch_bounds__(TPB)
edge_kernel(const int4* __restrict__ map0,   // mapping row 0, 4 edges per int4
            const int4* __restrict__ map1,   // mapping row 1
            const int4* __restrict__ batch,  // mapping_batch
            const float* __restrict__ ks,    // (4,25,25)
            const float* __restrict__ v0,    // (25,25)
            float* __restrict__ out,
            int nQuads, int quadsPerBlock) {
    __shared__ float4 s_k[625];  // k0..k3 per (t0,t1)
    __shared__ float  s_v[625];  // v0 per (t0,t1)
    for (int i = threadIdx.x; i < 625; i += TPB) {
        s_k[i] = make_float4(ks[i], ks[625 + i], ks[1250 + i], ks[1875 + i]);
        s_v[i] = v0[i];
    }
    __syncthreads();

    int pStart = blockIdx.x * quadsPerBlock + threadIdx.x;
    int pEnd   = min((blockIdx.x + 1) * quadsPerBlock, nQuads);

    // Register accumulator; mapping_batch is sorted so segment changes are
    // rare along a thread's walk -> few atomics (fire-and-forget REDG).
    float acc = 0.0f;
    int   cur = -1;

    for (int p = pStart; p < pEnd; p += TPB) {
        // Streamed index loads: evict-first, read once.
        int4 a = __ldcs(&map0[p]);
        int4 b = __ldcs(&map1[p]);
        int4 s = __ldcs(&batch[p]);

        // ---- all 8 gathers issued back-to-back: MLP = 8 ----
        float4 na0 = g_node[a.x];
        float4 na1 = g_node[a.y];
        float4 na2 = g_node[a.z];
        float4 na3 = g_node[a.w];
        float4 nb0 = g_node[b.x];
        float4 nb1 = g_node[b.y];
        float4 nb2 = g_node[b.z];
        float4 nb3 = g_node[b.w];

        // ---- branch-free compute of the 4 edge energies ----
        float V0 = poly(na0, nb0, s_k, s_v);
        float V1 = poly(na1, nb1, s_k, s_v);
        float V2 = poly(na2, nb2, s_k, s_v);
        float V3 = poly(na3, nb3, s_k, s_v);

        // ---- segment accumulation (rarely-taken branches) ----
        if (s.x != cur) {
            if (cur >= 0) atomicAdd(&out[cur], acc);
            acc = 0.0f; cur = s.x;
        }
        acc += V0;
        if (s.y != cur) { atomicAdd(&out[cur], acc); acc = 0.0f; cur = s.y; }
        acc += V1;
        if (s.z != cur) { atomicAdd(&out[cur], acc); acc = 0.0f; cur = s.z; }
        acc += V2;
        if (s.w != cur) { atomicAdd(&out[cur], acc); acc = 0.0f; cur = s.w; }
        acc += V3;
    }
    if (cur >= 0) atomicAdd(&out[cur], acc);
}

extern "C" void kernel_launch(void* const* d_in, const int* in_sizes, int n_in,
                              void* d_out, int out_size) {
    const float* pos     = (const float*)d_in[0];
    const float* ks      = (const float*)d_in[1];
    const float* v0      = (const float*)d_in[2];
    const int*   mapping = (const int*)d_in[3];   // JAX downcasts int64 -> int32
    const int*   types   = (const int*)d_in[4];
    const int*   batch   = (const int*)d_in[5];

    int N = in_sizes[0] / 3;          // 100000
    int E = in_sizes[3] / 2;          // 8,000,000
    int G = out_size;                 // 512
    float* out = (float*)d_out;

    if (N > N_MAX) N = N_MAX;  // defensive; problem shape is fixed

    int nQuads = E / 4;        // 2M

    int prepThreads = (N > G) ? N : G;
    prep_kernel<<<(prepThreads + TPB - 1) / TPB, TPB>>>(pos, types, N, out, G);

    // Target ~4 resident 256-thread blocks per SM -> single balanced wave.
    int grid = 592;  // 4 * 148
    int qpb  = (nQuads + grid - 1) / grid;
    qpb      = ((qpb + TPB - 1) / TPB) * TPB;  // multiple of block width
    grid     = (nQuads + qpb - 1) / qpb;

    edge_kernel<<<grid, TPB>>>((const int4*)mapping,
                               (const int4*)(mapping + E),
                               (const int4*)batch,
                               ks, v0, out, nQuads, qpb);
}